// round 15
// baseline (speedup 1.0000x reference)
#include <cuda_runtime.h>
#include <cuda_bf16.h>
#include <math.h>
#include <stdint.h>

#define B_    8
#define N_    2048
#define H_    256
#define ROWS_ (B_ * N_)
#define NT    256

// ---------------- device scratch ----------------
__device__ float g_s[ROWS_];
__device__ __align__(16) __nv_bfloat16 gW[2][H_ * H_];   // W1 limbs, split once

// ---------------- helpers ----------------
__device__ __forceinline__ uint32_t smem_u32(const void* p) {
    uint32_t a;
    asm("{ .reg .u64 t; cvta.to.shared.u64 t, %1; cvt.u32.u64 %0, t; }" : "=r"(a) : "l"(p));
    return a;
}
__device__ __forceinline__ void ldm4(uint32_t* r, uint32_t addr) {
    asm volatile("ldmatrix.sync.aligned.m8n8.x4.shared.b16 {%0,%1,%2,%3}, [%4];"
                 : "=r"(r[0]), "=r"(r[1]), "=r"(r[2]), "=r"(r[3]) : "r"(addr));
}
__device__ __forceinline__ void mma16816(float* c, const uint32_t* a, const uint32_t* b) {
    asm volatile(
        "mma.sync.aligned.m16n8k16.row.col.f32.bf16.bf16.f32 "
        "{%0,%1,%2,%3},{%4,%5,%6,%7},{%8,%9},{%0,%1,%2,%3};"
        : "+f"(c[0]), "+f"(c[1]), "+f"(c[2]), "+f"(c[3])
        : "r"(a[0]), "r"(a[1]), "r"(a[2]), "r"(a[3]), "r"(b[0]), "r"(b[1]));
}
__device__ __forceinline__ void cp16(uint32_t saddr, const void* gaddr) {
    asm volatile("cp.async.cg.shared.global [%0], [%1], 16;" :: "r"(saddr), "l"(gaddr));
}
#define CP_COMMIT() asm volatile("cp.async.commit_group;" ::: "memory")
#define CP_WAIT0()  asm volatile("cp.async.wait_group 0;" ::: "memory")

// split a float4 into hi-limb (4 bf16 in uint2) and lo-limb
__device__ __forceinline__ void split4(float4 v, uint2& hi, uint2& lo) {
    __nv_bfloat162 h0 = __nv_bfloat162(__float2bfloat16(v.x), __float2bfloat16(v.y));
    __nv_bfloat162 h1 = __nv_bfloat162(__float2bfloat16(v.z), __float2bfloat16(v.w));
    __nv_bfloat162 l0 = __nv_bfloat162(
        __float2bfloat16(v.x - __bfloat162float(h0.x)),
        __float2bfloat16(v.y - __bfloat162float(h0.y)));
    __nv_bfloat162 l1 = __nv_bfloat162(
        __float2bfloat16(v.z - __bfloat162float(h1.x)),
        __float2bfloat16(v.w - __bfloat162float(h1.y)));
    hi.x = *(uint32_t*)&h0;  hi.y = *(uint32_t*)&h1;
    lo.x = *(uint32_t*)&l0;  lo.y = *(uint32_t*)&l1;
}

// ---------------- conv_w: split W1 ONCE into gW limbs ----------------------
__global__ void __launch_bounds__(NT) conv_w(const float* __restrict__ W1) {
    int i = blockIdx.x * NT + threadIdx.x;            // one float4 per thread
    float4 v = ((const float4*)W1)[i];
    uint2 hi, lo;
    split4(v, hi, lo);
    *(uint2*)&gW[0][i * 4] = hi;
    *(uint2*)&gW[1][i * 4] = lo;
}

// ---------------- Phase A: full-chip bf16 2-limb mma.sync (R14 config) ------
// Launched in halves of 128 blocks (rows via row0) so phase B can overlap.
#define BM     64
#define AST    72
#define A_LIMB (BM * AST)                  // halves
#define B_LIMB (256 * AST)
#define A_BYTES (2 * A_LIMB * 2)           // 18432
#define B_BYTES (2 * B_LIMB * 2)           // 73728
#define SB_BASE A_BYTES
#define RED_BASE (SB_BASE + B_BYTES)       // 92160
#define SMEMSZ  (RED_BASE + BM * 4 * 4)    // 93184

__global__ void __launch_bounds__(NT, 2) mma_kernel(
    const float* __restrict__ h, const float* __restrict__ b1,
    const float* __restrict__ w2, int row0)
{
    extern __shared__ char smem[];
    const uint32_t sb = smem_u32(smem);
    float* red = (float*)(smem + RED_BASE);            // [BM][4]
    const int t = threadIdx.x, wid = t >> 5, lane = t & 31;
    const int rowBase = row0 + blockIdx.x * BM;
    const int mg = wid >> 2;                 // row group (0/1)
    const int nq = wid & 3;                  // col quarter

    const int arow = lane & 15, acg = lane >> 4;
    const int brow = (lane & 7) + 8 * (lane >> 4), bcg = (lane >> 3) & 1;

    uint32_t aaddr[2][2];                    // [limb][mtile]
#pragma unroll
    for (int s = 0; s < 2; s++)
#pragma unroll
        for (int mt = 0; mt < 2; mt++)
            aaddr[s][mt] = sb + (s * A_LIMB + (mg * 32 + mt * 16 + arow) * AST + acg * 8) * 2;

    float acc[2][8][4];
#pragma unroll
    for (int mt = 0; mt < 2; mt++)
#pragma unroll
        for (int nt = 0; nt < 8; nt++)
#pragma unroll
            for (int e = 0; e < 4; e++) acc[mt][nt][e] = 0.f;

#pragma unroll 1
    for (int kc = 0; kc < 4; kc++) {
        const int ko = kc * 64;
#pragma unroll
        for (int s = 0; s < 2; s++)
#pragma unroll 8
            for (int u = t; u < 2048; u += NT) {          // B: 256 rows x 8 q
                int row = u >> 3, q = u & 7;
                cp16(sb + SB_BASE + (s * B_LIMB + row * AST + q * 8) * 2,
                     &gW[s][(size_t)row * H_ + ko + q * 8]);
            }
        CP_COMMIT();
#pragma unroll
        for (int u = t; u < 1024; u += NT) {              // A: 64 rows x 16 q
            int row = u >> 4, q = u & 15;
            float4 v = *(const float4*)&h[(size_t)(rowBase + row) * H_ + ko + q * 4];
            uint2 hi, lo;
            split4(v, hi, lo);
            char* dst = smem + (row * AST + q * 4) * 2;
            *(uint2*)(dst) = hi;
            *(uint2*)(dst + A_LIMB * 2) = lo;
        }
        CP_WAIT0();
        __syncthreads();

#pragma unroll
        for (int ks = 0; ks < 4; ks++) {
            uint32_t a[2][2][4];
#pragma unroll
            for (int s = 0; s < 2; s++) {
                ldm4(a[s][0], aaddr[s][0] + ks * 32);
                ldm4(a[s][1], aaddr[s][1] + ks * 32);
            }
            uint32_t b[2][8][2];
#pragma unroll
            for (int s = 0; s < 2; s++)
#pragma unroll
                for (int p = 0; p < 4; p++) {
                    uint32_t r[4];
                    uint32_t ba = sb + SB_BASE +
                        (s * B_LIMB + (nq * 64 + p * 16 + brow) * AST + bcg * 8 + ks * 16) * 2;
                    ldm4(r, ba);
                    b[s][p * 2][0] = r[0];      b[s][p * 2][1] = r[1];
                    b[s][p * 2 + 1][0] = r[2];  b[s][p * 2 + 1][1] = r[3];
                }
#pragma unroll
            for (int mt = 0; mt < 2; mt++)
#pragma unroll
                for (int nt = 0; nt < 8; nt++) {
                    float* c = acc[mt][nt];
                    mma16816(c, a[0][mt], b[0][nt]);   // hi*hi
                    mma16816(c, a[0][mt], b[1][nt]);   // hi*lo
                    mma16816(c, a[1][mt], b[0][nt]);   // lo*hi
                }
        }
        __syncthreads();
    }

    // ---- epilogue ----
#pragma unroll
    for (int mt = 0; mt < 2; mt++) {
        float p0 = 0.f, p1 = 0.f;
#pragma unroll
        for (int nt = 0; nt < 8; nt++) {
            const int c0 = nq * 64 + nt * 8 + 2 * (lane & 3);
            const float bb0 = __ldg(b1 + c0), bb1 = __ldg(b1 + c0 + 1);
            const float ww0 = __ldg(w2 + c0), ww1 = __ldg(w2 + c0 + 1);
            float v;
            v = acc[mt][nt][0] + bb0;  p0 += (v / (1.f + __expf(-v))) * ww0;
            v = acc[mt][nt][1] + bb1;  p0 += (v / (1.f + __expf(-v))) * ww1;
            v = acc[mt][nt][2] + bb0;  p1 += (v / (1.f + __expf(-v))) * ww0;
            v = acc[mt][nt][3] + bb1;  p1 += (v / (1.f + __expf(-v))) * ww1;
        }
        p0 += __shfl_xor_sync(0xFFFFFFFF, p0, 1);
        p0 += __shfl_xor_sync(0xFFFFFFFF, p0, 2);
        p1 += __shfl_xor_sync(0xFFFFFFFF, p1, 1);
        p1 += __shfl_xor_sync(0xFFFFFFFF, p1, 2);
        if ((lane & 3) == 0) {
            int rr = mg * 32 + mt * 16 + (lane >> 2);
            red[rr * 4 + nq] = p0;
            red[(rr + 8) * 4 + nq] = p1;
        }
    }
    __syncthreads();
    if (t < BM) {
        const float* rp = &red[t * 4];
        g_s[rowBase + t] = (rp[0] + rp[1]) + (rp[2] + rp[3]);
    }
}

// ---------------- Phase B: out[b,i,j] = truncf(s_i - s_j + b2) as float -----
// (proven R4 config; b0 = batch offset for half-launches)
__global__ void __launch_bounds__(NT) out_kernel(
    const float* __restrict__ b2p, float* __restrict__ out, int b0)
{
    const int t = threadIdx.x;
    const int i = blockIdx.x;
    const int b = b0 + blockIdx.y;
    const float* sbp = g_s + b * N_;
    const float sib = sbp[i] + __ldg(b2p);
    const int j0 = t * 8;
    float4 p0 = *(const float4*)(sbp + j0);
    float4 p1 = *(const float4*)(sbp + j0 + 4);
    float4 v0, v1;
    v0.x = truncf(sib - p0.x);  v0.y = truncf(sib - p0.y);
    v0.z = truncf(sib - p0.z);  v0.w = truncf(sib - p0.w);
    v1.x = truncf(sib - p1.x);  v1.y = truncf(sib - p1.y);
    v1.z = truncf(sib - p1.z);  v1.w = truncf(sib - p1.w);
    const size_t base = ((size_t)(b * N_ + i)) * N_ + j0;
    *(float4*)(out + base)     = v0;
    *(float4*)(out + base + 4) = v1;
}

extern "C" void kernel_launch(void* const* d_in, const int* in_sizes, int n_in,
                              void* d_out, int out_size)
{
    const float *h = 0, *W1 = 0, *b1 = 0, *w2 = 0, *b2 = 0;
    for (int idx = 0; idx < n_in; ++idx) {
        const int sz = in_sizes[idx];
        if (sz == ROWS_ * H_)      h  = (const float*)d_in[idx];
        else if (sz == H_ * H_)    W1 = (const float*)d_in[idx];
        else if (sz == H_) {
            if (!b1) b1 = (const float*)d_in[idx];
            else if (!w2) w2 = (const float*)d_in[idx];
        }
        else if (sz == 1)          b2 = (const float*)d_in[idx];
    }
    (void)out_size;
    float* out = (float*)d_out;

    // one-time setup (first call is the non-captured correctness run)
    static int init_done = 0;
    static cudaStream_t s2 = 0;
    static cudaEvent_t ev0 = 0, ev1 = 0, ev2 = 0;
    static int fork_ok = 0;
    if (!init_done) {
        cudaFuncSetAttribute(mma_kernel, cudaFuncAttributeMaxDynamicSharedMemorySize, SMEMSZ);
        fork_ok = (cudaStreamCreateWithFlags(&s2, cudaStreamNonBlocking) == cudaSuccess)
               && (cudaEventCreateWithFlags(&ev0, cudaEventDisableTiming) == cudaSuccess)
               && (cudaEventCreateWithFlags(&ev1, cudaEventDisableTiming) == cudaSuccess)
               && (cudaEventCreateWithFlags(&ev2, cudaEventDisableTiming) == cudaSuccess);
        init_done = 1;
    }

    conv_w<<<H_ * H_ / 4 / NT, NT>>>(W1);

    if (fork_ok) {
        // fork-join DAG: out half0 overlaps mma half1
        mma_kernel<<<128, NT, SMEMSZ>>>(h, b1, w2, 0);
        cudaEventRecord(ev0, 0);
        mma_kernel<<<128, NT, SMEMSZ>>>(h, b1, w2, ROWS_ / 2);
        cudaEventRecord(ev1, 0);
        cudaStreamWaitEvent(s2, ev0, 0);
        out_kernel<<<dim3(N_, B_ / 2), NT, 0, s2>>>(b2, out, 0);
        cudaStreamWaitEvent(s2, ev1, 0);
        out_kernel<<<dim3(N_, B_ / 2), NT, 0, s2>>>(b2, out, B_ / 2);
        cudaEventRecord(ev2, s2);
        cudaStreamWaitEvent(0, ev2, 0);
    } else {
        // sequential fallback (R14 behavior)
        mma_kernel<<<128, NT, SMEMSZ>>>(h, b1, w2, 0);
        mma_kernel<<<128, NT, SMEMSZ>>>(h, b1, w2, ROWS_ / 2);
        out_kernel<<<dim3(N_, B_), NT>>>(b2, out, 0);
    }
}

// round 17
// speedup vs baseline: 1.1465x; 1.1465x over previous
#include <cuda_runtime.h>
#include <cuda_bf16.h>
#include <math.h>
#include <stdint.h>

#define B_    8
#define N_    2048
#define H_    256
#define ROWS_ (B_ * N_)
#define NT    256

// ---------------- device scratch ----------------
__device__ float g_s[ROWS_];
__device__ __align__(16) __nv_bfloat16 gW[2][H_ * H_];   // W1 limbs
__device__ int g_wcnt = 0;          // W-split gate; reset by out_kernel each replay

// ---------------- helpers ----------------
__device__ __forceinline__ uint32_t smem_u32(const void* p) {
    uint32_t a;
    asm("{ .reg .u64 t; cvta.to.shared.u64 t, %1; cvt.u32.u64 %0, t; }" : "=r"(a) : "l"(p));
    return a;
}
__device__ __forceinline__ void ldm4(uint32_t* r, uint32_t addr) {
    asm volatile("ldmatrix.sync.aligned.m8n8.x4.shared.b16 {%0,%1,%2,%3}, [%4];"
                 : "=r"(r[0]), "=r"(r[1]), "=r"(r[2]), "=r"(r[3]) : "r"(addr));
}
__device__ __forceinline__ void mma16816(float* c, const uint32_t* a, const uint32_t* b) {
    asm volatile(
        "mma.sync.aligned.m16n8k16.row.col.f32.bf16.bf16.f32 "
        "{%0,%1,%2,%3},{%4,%5,%6,%7},{%8,%9},{%0,%1,%2,%3};"
        : "+f"(c[0]), "+f"(c[1]), "+f"(c[2]), "+f"(c[3])
        : "r"(a[0]), "r"(a[1]), "r"(a[2]), "r"(a[3]), "r"(b[0]), "r"(b[1]));
}
__device__ __forceinline__ void cp16(uint32_t saddr, const void* gaddr) {
    asm volatile("cp.async.cg.shared.global [%0], [%1], 16;" :: "r"(saddr), "l"(gaddr));
}
#define CP_COMMIT() asm volatile("cp.async.commit_group;" ::: "memory")
#define CP_WAIT0()  asm volatile("cp.async.wait_group 0;" ::: "memory")

// split a float4 into hi-limb (4 bf16 in uint2) and lo-limb
__device__ __forceinline__ void split4(float4 v, uint2& hi, uint2& lo) {
    __nv_bfloat162 h0 = __nv_bfloat162(__float2bfloat16(v.x), __float2bfloat16(v.y));
    __nv_bfloat162 h1 = __nv_bfloat162(__float2bfloat16(v.z), __float2bfloat16(v.w));
    __nv_bfloat162 l0 = __nv_bfloat162(
        __float2bfloat16(v.x - __bfloat162float(h0.x)),
        __float2bfloat16(v.y - __bfloat162float(h0.y)));
    __nv_bfloat162 l1 = __nv_bfloat162(
        __float2bfloat16(v.z - __bfloat162float(h1.x)),
        __float2bfloat16(v.w - __bfloat162float(h1.y)));
    hi.x = *(uint32_t*)&h0;  hi.y = *(uint32_t*)&h1;
    lo.x = *(uint32_t*)&l0;  lo.y = *(uint32_t*)&l1;
}

// ---------------- Phase A: full-chip bf16 2-limb mma.sync (R14 tile config)
// + fused W1 split behind an all-resident producer gate.
// 256 blocks x 256 threads, 2 blocks/SM (93 KB x 2 <= 227 KB; 256 <= 296
// resident slots -> spin-gate is deadlock-free).
// Blocks 0..63 split 1/64 of W1 each into gW, then everyone gates on g_wcnt.
#define BM     64
#define AST    72
#define A_LIMB (BM * AST)                  // halves
#define B_LIMB (256 * AST)
#define A_BYTES (2 * A_LIMB * 2)           // 18432
#define B_BYTES (2 * B_LIMB * 2)           // 73728
#define SB_BASE A_BYTES
#define RED_BASE (SB_BASE + B_BYTES)       // 92160
#define SMEMSZ  (RED_BASE + BM * 4 * 4)    // 93184

__global__ void __launch_bounds__(NT, 2) mma_kernel(
    const float* __restrict__ h, const float* __restrict__ W1,
    const float* __restrict__ b1, const float* __restrict__ w2)
{
    extern __shared__ char smem[];
    const uint32_t sb = smem_u32(smem);
    float* red = (float*)(smem + RED_BASE);            // [BM][4]
    const int t = threadIdx.x, wid = t >> 5, lane = t & 31;
    const int rowBase = blockIdx.x * BM;
    const int mg = wid >> 2;                 // row group (0/1)
    const int nq = wid & 3;                  // col quarter

    // ---- fused W1 split: blocks 0..63, one float4 per thread --------------
    if (blockIdx.x < 64) {
        int i = blockIdx.x * NT + t;                    // covers all of W1/4
        float4 v = ((const float4*)W1)[i];
        uint2 hi, lo;
        split4(v, hi, lo);
        *(uint2*)&gW[0][i * 4] = hi;
        *(uint2*)&gW[1][i * 4] = lo;
        __threadfence();
        __syncthreads();
        if (t == 0) atomicAdd(&g_wcnt, 1);
    }
    // ---- gate: wait until all 64 splitter blocks have published ----------
    if (t == 0) {
        volatile int* c = &g_wcnt;
        while (*c < 64) { __nanosleep(100); }
    }
    __syncthreads();
    __threadfence();     // order gW reads after the observed count

    const int arow = lane & 15, acg = lane >> 4;
    const int brow = (lane & 7) + 8 * (lane >> 4), bcg = (lane >> 3) & 1;

    uint32_t aaddr[2][2];                    // [limb][mtile]
#pragma unroll
    for (int s = 0; s < 2; s++)
#pragma unroll
        for (int mt = 0; mt < 2; mt++)
            aaddr[s][mt] = sb + (s * A_LIMB + (mg * 32 + mt * 16 + arow) * AST + acg * 8) * 2;

    float acc[2][8][4];
#pragma unroll
    for (int mt = 0; mt < 2; mt++)
#pragma unroll
        for (int nt = 0; nt < 8; nt++)
#pragma unroll
            for (int e = 0; e < 4; e++) acc[mt][nt][e] = 0.f;

#pragma unroll 1
    for (int kc = 0; kc < 4; kc++) {
        const int ko = kc * 64;
#pragma unroll
        for (int s = 0; s < 2; s++)
#pragma unroll 8
            for (int u = t; u < 2048; u += NT) {          // B: 256 rows x 8 q
                int row = u >> 3, q = u & 7;
                cp16(sb + SB_BASE + (s * B_LIMB + row * AST + q * 8) * 2,
                     &gW[s][(size_t)row * H_ + ko + q * 8]);
            }
        CP_COMMIT();
#pragma unroll
        for (int u = t; u < 1024; u += NT) {              // A: 64 rows x 16 q
            int row = u >> 4, q = u & 15;
            float4 v = *(const float4*)&h[(size_t)(rowBase + row) * H_ + ko + q * 4];
            uint2 hi, lo;
            split4(v, hi, lo);
            char* dst = smem + (row * AST + q * 4) * 2;
            *(uint2*)(dst) = hi;
            *(uint2*)(dst + A_LIMB * 2) = lo;
        }
        CP_WAIT0();
        __syncthreads();

#pragma unroll
        for (int ks = 0; ks < 4; ks++) {
            uint32_t a[2][2][4];
#pragma unroll
            for (int s = 0; s < 2; s++) {
                ldm4(a[s][0], aaddr[s][0] + ks * 32);
                ldm4(a[s][1], aaddr[s][1] + ks * 32);
            }
            uint32_t b[2][8][2];
#pragma unroll
            for (int s = 0; s < 2; s++)
#pragma unroll
                for (int p = 0; p < 4; p++) {
                    uint32_t r[4];
                    uint32_t ba = sb + SB_BASE +
                        (s * B_LIMB + (nq * 64 + p * 16 + brow) * AST + bcg * 8 + ks * 16) * 2;
                    ldm4(r, ba);
                    b[s][p * 2][0] = r[0];      b[s][p * 2][1] = r[1];
                    b[s][p * 2 + 1][0] = r[2];  b[s][p * 2 + 1][1] = r[3];
                }
#pragma unroll
            for (int mt = 0; mt < 2; mt++)
#pragma unroll
                for (int nt = 0; nt < 8; nt++) {
                    float* c = acc[mt][nt];
                    mma16816(c, a[0][mt], b[0][nt]);   // hi*hi
                    mma16816(c, a[0][mt], b[1][nt]);   // hi*lo
                    mma16816(c, a[1][mt], b[0][nt]);   // lo*hi
                }
        }
        __syncthreads();
    }

    // ---- epilogue: silu(x+b1)*w2 partial dot over this warp's 64 cols -----
#pragma unroll
    for (int mt = 0; mt < 2; mt++) {
        float p0 = 0.f, p1 = 0.f;
#pragma unroll
        for (int nt = 0; nt < 8; nt++) {
            const int c0 = nq * 64 + nt * 8 + 2 * (lane & 3);
            const float bb0 = __ldg(b1 + c0), bb1 = __ldg(b1 + c0 + 1);
            const float ww0 = __ldg(w2 + c0), ww1 = __ldg(w2 + c0 + 1);
            float v;
            v = acc[mt][nt][0] + bb0;  p0 += (v / (1.f + __expf(-v))) * ww0;
            v = acc[mt][nt][1] + bb1;  p0 += (v / (1.f + __expf(-v))) * ww1;
            v = acc[mt][nt][2] + bb0;  p1 += (v / (1.f + __expf(-v))) * ww0;
            v = acc[mt][nt][3] + bb1;  p1 += (v / (1.f + __expf(-v))) * ww1;
        }
        p0 += __shfl_xor_sync(0xFFFFFFFF, p0, 1);
        p0 += __shfl_xor_sync(0xFFFFFFFF, p0, 2);
        p1 += __shfl_xor_sync(0xFFFFFFFF, p1, 1);
        p1 += __shfl_xor_sync(0xFFFFFFFF, p1, 2);
        if ((lane & 3) == 0) {
            int rr = mg * 32 + mt * 16 + (lane >> 2);
            red[rr * 4 + nq] = p0;
            red[(rr + 8) * 4 + nq] = p1;
        }
    }
    __syncthreads();
    if (t < BM) {
        const float* rp = &red[t * 4];
        g_s[rowBase + t] = (rp[0] + rp[1]) + (rp[2] + rp[3]);
    }
}

// ---------------- Phase B: out[b,i,j] = truncf(s_i - s_j + b2) as float -----
// (proven R4 config). Also resets the W-split gate for the next graph replay
// (stream-ordered after all mma blocks -> safe, deterministic).
__global__ void __launch_bounds__(NT) out_kernel(
    const float* __restrict__ b2p, float* __restrict__ out)
{
    const int t = threadIdx.x;
    const int i = blockIdx.x;
    const int b = blockIdx.y;
    if (i == 0 && b == 0 && t == 0) g_wcnt = 0;
    const float* sbp = g_s + b * N_;
    const float sib = sbp[i] + __ldg(b2p);
    const int j0 = t * 8;
    float4 p0 = *(const float4*)(sbp + j0);
    float4 p1 = *(const float4*)(sbp + j0 + 4);
    float4 v0, v1;
    v0.x = truncf(sib - p0.x);  v0.y = truncf(sib - p0.y);
    v0.z = truncf(sib - p0.z);  v0.w = truncf(sib - p0.w);
    v1.x = truncf(sib - p1.x);  v1.y = truncf(sib - p1.y);
    v1.z = truncf(sib - p1.z);  v1.w = truncf(sib - p1.w);
    const size_t base = ((size_t)(b * N_ + i)) * N_ + j0;
    *(float4*)(out + base)     = v0;
    *(float4*)(out + base + 4) = v1;
}

extern "C" void kernel_launch(void* const* d_in, const int* in_sizes, int n_in,
                              void* d_out, int out_size)
{
    const float *h = 0, *W1 = 0, *b1 = 0, *w2 = 0, *b2 = 0;
    for (int idx = 0; idx < n_in; ++idx) {
        const int sz = in_sizes[idx];
        if (sz == ROWS_ * H_)      h  = (const float*)d_in[idx];
        else if (sz == H_ * H_)    W1 = (const float*)d_in[idx];
        else if (sz == H_) {
            if (!b1) b1 = (const float*)d_in[idx];
            else if (!w2) w2 = (const float*)d_in[idx];
        }
        else if (sz == 1)          b2 = (const float*)d_in[idx];
    }
    (void)out_size;

    static int attr_set = 0;
    if (!attr_set) {
        cudaFuncSetAttribute(mma_kernel, cudaFuncAttributeMaxDynamicSharedMemorySize, SMEMSZ);
        attr_set = 1;
    }

    mma_kernel<<<ROWS_ / BM, NT, SMEMSZ>>>(h, W1, b1, w2);
    out_kernel<<<dim3(N_, B_), NT>>>(b2, (float*)d_out);
}